// round 1
// baseline (speedup 1.0000x reference)
#include <cuda_runtime.h>

#define N_SEG 8192
#define D 64
#define SCAN_THREADS 1024
#define ELEMS_PER_THREAD (N_SEG / SCAN_THREADS)   // 8

// Scratch: exclusive prefix offsets, g_off[N_SEG] = total rows.
__device__ int g_off[N_SEG + 1];

// ---------------------------------------------------------------------------
// Kernel 1: exclusive prefix scan of lengths -> g_off.
// Auto-detects int64 vs int32 storage of `lengths`:
//   all lengths are in [68,188] (nonzero), so if the raw int32 word at index 1
//   is 0, the buffer is little-endian int64 (high word of lengths[0]) -> read
//   every other word; otherwise it is int32 -> read densely.
// ---------------------------------------------------------------------------
__global__ void __launch_bounds__(SCAN_THREADS)
scan_kernel(const int* __restrict__ lenraw) {
    const int stride = (lenraw[1] == 0) ? 2 : 1;
    const int tid = threadIdx.x;

    int vals[ELEMS_PER_THREAD];
    int local = 0;
#pragma unroll
    for (int i = 0; i < ELEMS_PER_THREAD; i++) {
        const int idx = tid * ELEMS_PER_THREAD + i;
        const int v = lenraw[idx * stride];
        vals[i] = local;       // exclusive within thread
        local += v;
    }

    const int lane = tid & 31;
    const int wid  = tid >> 5;

    // inclusive warp scan of per-thread totals
    int x = local;
#pragma unroll
    for (int off = 1; off < 32; off <<= 1) {
        const int y = __shfl_up_sync(0xFFFFFFFFu, x, off);
        if (lane >= off) x += y;
    }

    __shared__ int wsum[32];
    if (lane == 31) wsum[wid] = x;
    __syncthreads();

    if (wid == 0) {
        int s = wsum[lane];
#pragma unroll
        for (int off = 1; off < 32; off <<= 1) {
            const int y = __shfl_up_sync(0xFFFFFFFFu, s, off);
            if (lane >= off) s += y;
        }
        wsum[lane] = s;        // inclusive warp totals
    }
    __syncthreads();

    const int base = (x - local) + (wid > 0 ? wsum[wid - 1] : 0);
#pragma unroll
    for (int i = 0; i < ELEMS_PER_THREAD; i++)
        g_off[tid * ELEMS_PER_THREAD + i] = base + vals[i];
    if (tid == SCAN_THREADS - 1)
        g_off[N_SEG] = base + local;
}

// ---------------------------------------------------------------------------
// Kernel 2: one CTA per segment.
// Thread t: column-group cg = t & 15 (float4, 16 groups cover D=64),
//           row-group   rg = t >> 4 (rows rg, rg+16, ...).
// Each half-warp reads one contiguous 256 B row -> fully coalesced LDG.128.
// __ldcs: data is read exactly once, keep it out of L2's way.
// ---------------------------------------------------------------------------
__global__ void __launch_bounds__(256)
seg_sum_kernel(const float4* __restrict__ data, float4* __restrict__ out) {
    const int s = blockIdx.x;
    const int start = g_off[s];
    const int len   = g_off[s + 1] - start;

    const int t  = threadIdx.x;
    const int cg = t & 15;
    const int rg = t >> 4;

    const float4* __restrict__ base = data + (size_t)start * 16 + cg;

    float4 acc = make_float4(0.f, 0.f, 0.f, 0.f);
#pragma unroll 4
    for (int r = rg; r < len; r += 16) {
        const float4 v = __ldcs(&base[(size_t)r * 16]);
        acc.x += v.x; acc.y += v.y; acc.z += v.z; acc.w += v.w;
    }

    __shared__ float4 red[256];
    red[t] = acc;
    __syncthreads();

#pragma unroll
    for (int str = 128; str >= 32; str >>= 1) {
        if (t < str) {
            float4 a = red[t];
            const float4 b = red[t + str];
            a.x += b.x; a.y += b.y; a.z += b.z; a.w += b.w;
            red[t] = a;
        }
        __syncthreads();
    }
    if (t < 16) {
        float4 a = red[t];
        const float4 b = red[t + 16];
        a.x += b.x; a.y += b.y; a.z += b.z; a.w += b.w;
        out[(size_t)s * 16 + t] = a;
    }
}

// ---------------------------------------------------------------------------
extern "C" void kernel_launch(void* const* d_in, const int* in_sizes, int n_in,
                              void* d_out, int out_size) {
    const float* data  = (const float*)d_in[0];
    const int*   lenrw = (const int*)d_in[1];   // int32 view; scan auto-detects i64
    float*       out   = (float*)d_out;

    scan_kernel<<<1, SCAN_THREADS>>>(lenrw);
    seg_sum_kernel<<<N_SEG, 256>>>((const float4*)data, (float4*)out);
}